// round 3
// baseline (speedup 1.0000x reference)
#include <cuda_runtime.h>

// Problem constants
#define Bb   16
#define Nn   4096
#define Dd   1024
#define Hh   512
#define Cc   4
#define Ss   64                 // chunks per bag (smaller tail quantum)
#define ROWS (Nn / Ss)          // 64 rows per chunk
#define TPB  256
#define Gg   (Bb * Ss)          // 1024 pass1 CTAs
#define WCB  384                // Wc CTAs (8 W1-rows each)
#define BR   8                  // rows per batch in pass1
#define NB   (ROWS / BR)        // 8 batches per CTA
#define KSL  6                  // k2 slices per bag

// ---------------- scratch (static device arrays; no cudaMalloc) -------------
__device__ float g_Pm[Gg];
__device__ float g_Pl[Gg];
__device__ float g_Pacc[Gg][Dd];
__device__ float g_Psum[Gg][Dd];
__device__ float g_Pmx[Gg][Dd];
__device__ float g_Wc[3 * Dd][Cc];     // W1 @ W2 (head is affine: no ReLU)
__device__ float g_outp[Bb][KSL][Cc];  // per-slice partial outputs

// ============================================================================
// K1: fused [pass1 online-softmax pooling] + [Wc = W1 @ W2]
// ============================================================================
__global__ __launch_bounds__(TPB) void k1_kernel(
    const float* __restrict__ bags, const float* __restrict__ query,
    const float* __restrict__ W1,   const float* __restrict__ W2)
{
    const int blk = blockIdx.x;
    const int tid = threadIdx.x;

    if (blk < Gg) {
        // -------- pass1: one (bag, chunk) of 64 rows; thread t owns 4 d-slots
        const int b = blk >> 6;            // / Ss
        const int s = blk & (Ss - 1);

        __shared__ float sd[BR][8];        // [row][warp] partial dots
        __shared__ __align__(16) float ssc[BR];  // final scores (warp0-built)

        const float4 q = reinterpret_cast<const float4*>(query)[tid];

        float4 acc = make_float4(0.f, 0.f, 0.f, 0.f);
        float4 sum = make_float4(0.f, 0.f, 0.f, 0.f);
        float4 mxv = make_float4(-1e30f, -1e30f, -1e30f, -1e30f);
        float  m = -1e30f, l = 0.f;

        const long long rowbase = ((long long)b * Nn + (long long)s * ROWS);
        const float4* bp = reinterpret_cast<const float4*>(bags)
                         + rowbase * (Dd / 4) + tid;

        const int w    = tid >> 5;
        const int lane = tid & 31;

        // software pipeline: x[cur] processed while x[next] loads pre-barrier
        float4 x[2][BR];
        #pragma unroll
        for (int i = 0; i < BR; i++)
            x[0][i] = bp[(long long)i * (Dd / 4)];

        #pragma unroll
        for (int bt = 0; bt < NB; bt++) {
            const int cur = bt & 1;

            float p[BR];
            #pragma unroll
            for (int i = 0; i < BR; i++)
                p[i] = x[cur][i].x * q.x + x[cur][i].y * q.y
                     + x[cur][i].z * q.z + x[cur][i].w * q.w;

            #pragma unroll
            for (int o = 16; o > 0; o >>= 1)
                #pragma unroll
                for (int i = 0; i < BR; i++)
                    p[i] += __shfl_xor_sync(0xffffffffu, p[i], o);

            if (lane == 0)
                #pragma unroll
                for (int i = 0; i < BR; i++) sd[i][w] = p[i];

            // prefetch next batch BEFORE the barrier: overlaps DRAM latency
            // with the reduce/barrier sequence (compiler can't hoist past BAR)
            if (bt + 1 < NB) {
                #pragma unroll
                for (int i = 0; i < BR; i++)
                    x[cur ^ 1][i] = bp[(long long)((bt + 1) * BR + i) * (Dd / 4)];
            }

            __syncthreads();
            if (w == 0 && lane < BR) {     // stage-2: 8 lanes sum 8 partials
                float t = 0.f;
                #pragma unroll
                for (int ww = 0; ww < 8; ww++) t += sd[lane][ww];
                ssc[lane] = t;
            }
            __syncthreads();

            float sc[BR];                  // 2x LDS.128 broadcast
            const float4 s03 = *reinterpret_cast<const float4*>(&ssc[0]);
            const float4 s47 = *reinterpret_cast<const float4*>(&ssc[4]);
            sc[0] = s03.x; sc[1] = s03.y; sc[2] = s03.z; sc[3] = s03.w;
            sc[4] = s47.x; sc[5] = s47.y; sc[6] = s47.z; sc[7] = s47.w;

            // batch-max online softmax: one rescale per 8 rows
            float bm = sc[0];
            #pragma unroll
            for (int i = 1; i < BR; i++) bm = fmaxf(bm, sc[i]);
            const float mn   = fmaxf(m, bm);
            const float corr = __expf(m - mn);
            float e[BR];
            #pragma unroll
            for (int i = 0; i < BR; i++) e[i] = __expf(sc[i] - mn);

            l *= corr;
            acc.x *= corr; acc.y *= corr; acc.z *= corr; acc.w *= corr;
            #pragma unroll
            for (int i = 0; i < BR; i++) {
                l += e[i];
                acc.x += e[i] * x[cur][i].x; acc.y += e[i] * x[cur][i].y;
                acc.z += e[i] * x[cur][i].z; acc.w += e[i] * x[cur][i].w;
                sum.x += x[cur][i].x; sum.y += x[cur][i].y;
                sum.z += x[cur][i].z; sum.w += x[cur][i].w;
                mxv.x = fmaxf(mxv.x, x[cur][i].x);
                mxv.y = fmaxf(mxv.y, x[cur][i].y);
                mxv.z = fmaxf(mxv.z, x[cur][i].z);
                mxv.w = fmaxf(mxv.w, x[cur][i].w);
            }
            m = mn;
        }

        reinterpret_cast<float4*>(g_Pacc[blk])[tid] = acc;
        reinterpret_cast<float4*>(g_Psum[blk])[tid] = sum;
        reinterpret_cast<float4*>(g_Pmx[blk])[tid]  = mxv;
        if (tid == 0) { g_Pm[blk] = m; g_Pl[blk] = l; }
    } else {
        // -------- Wc = W1 @ W2: one warp per W1 row --------------------------
        __shared__ float sW2[Cc][Hh];
        for (int i = tid; i < Hh * Cc; i += TPB) sW2[i & 3][i >> 2] = W2[i];
        __syncthreads();

        const int d    = (blk - Gg) * 8 + (tid >> 5);
        const int lane = tid & 31;
        const float* row = W1 + (long long)d * Hh;

        float a0 = 0.f, a1 = 0.f, a2 = 0.f, a3 = 0.f;
        for (int j = lane; j < Hh; j += 32) {
            const float wv = row[j];
            a0 += wv * sW2[0][j]; a1 += wv * sW2[1][j];
            a2 += wv * sW2[2][j]; a3 += wv * sW2[3][j];
        }
        #pragma unroll
        for (int o = 16; o > 0; o >>= 1) {
            a0 += __shfl_xor_sync(0xffffffffu, a0, o);
            a1 += __shfl_xor_sync(0xffffffffu, a1, o);
            a2 += __shfl_xor_sync(0xffffffffu, a2, o);
            a3 += __shfl_xor_sync(0xffffffffu, a3, o);
        }
        if (lane == 0)
            reinterpret_cast<float4*>(g_Wc)[d] = make_float4(a0, a1, a2, a3);
    }
}

// ============================================================================
// K2: merge chunk partials + dot with Wc. grid = Bb*KSL (96) blocks x 128 thr.
//   block (b, j): sec = j>>1 (0 mean, 1 max, 2 attn), 128 float4 X-slots.
//   Writes partial 4-vector to g_outp[b][j]. Block (b,0) also folds b1@W2.
// ============================================================================
__global__ __launch_bounds__(128) void k2_kernel(
    const float* __restrict__ b1, const float* __restrict__ W2)
{
    const int b   = blockIdx.x / KSL;
    const int j   = blockIdx.x % KSL;
    const int tid = threadIdx.x;
    const int sec = j >> 1;
    const int d4  = (j & 1) * 128 + tid;    // float4 slot within section
    const int g0  = b * Ss;

    float4 v;
    if (sec == 0) {
        float4 a = make_float4(0.f, 0.f, 0.f, 0.f);
        #pragma unroll 8
        for (int s = 0; s < Ss; s++) {
            float4 u = reinterpret_cast<const float4*>(g_Psum[g0 + s])[d4];
            a.x += u.x; a.y += u.y; a.z += u.z; a.w += u.w;
        }
        const float invN = 1.f / (float)Nn;
        v = make_float4(a.x * invN, a.y * invN, a.z * invN, a.w * invN);
    } else if (sec == 1) {
        float4 a = make_float4(-1e30f, -1e30f, -1e30f, -1e30f);
        #pragma unroll 8
        for (int s = 0; s < Ss; s++) {
            float4 u = reinterpret_cast<const float4*>(g_Pmx[g0 + s])[d4];
            a.x = fmaxf(a.x, u.x); a.y = fmaxf(a.y, u.y);
            a.z = fmaxf(a.z, u.z); a.w = fmaxf(a.w, u.w);
        }
        v = a;
    } else {
        float M = -1e30f;
        #pragma unroll 8
        for (int s = 0; s < Ss; s++) M = fmaxf(M, g_Pm[g0 + s]);
        float L = 0.f;
        #pragma unroll 8
        for (int s = 0; s < Ss; s++) L += g_Pl[g0 + s] * __expf(g_Pm[g0 + s] - M);
        float4 a = make_float4(0.f, 0.f, 0.f, 0.f);
        #pragma unroll 8
        for (int s = 0; s < Ss; s++) {
            const float we = __expf(g_Pm[g0 + s] - M);
            float4 u = reinterpret_cast<const float4*>(g_Pacc[g0 + s])[d4];
            a.x += u.x * we; a.y += u.y * we; a.z += u.z * we; a.w += u.w * we;
        }
        const float invL = 1.f / L;
        v = make_float4(a.x * invL, a.y * invL, a.z * invL, a.w * invL);
    }

    // dot with 4 Wc rows for this thread's 4 d-slots
    const int    rbase = sec * Dd + d4 * 4;
    const float4 w0 = reinterpret_cast<const float4*>(g_Wc)[rbase + 0];
    const float4 w1 = reinterpret_cast<const float4*>(g_Wc)[rbase + 1];
    const float4 w2 = reinterpret_cast<const float4*>(g_Wc)[rbase + 2];
    const float4 w3 = reinterpret_cast<const float4*>(g_Wc)[rbase + 3];
    float o0 = v.x * w0.x + v.y * w1.x + v.z * w2.x + v.w * w3.x;
    float o1 = v.x * w0.y + v.y * w1.y + v.z * w2.y + v.w * w3.y;
    float o2 = v.x * w0.z + v.y * w1.z + v.z * w2.z + v.w * w3.z;
    float o3 = v.x * w0.w + v.y * w1.w + v.z * w2.w + v.w * w3.w;

    // block (b, 0) additionally folds the bias term b1 @ W2 (4 j's per thread)
    if (j == 0) {
        #pragma unroll
        for (int k = 0; k < 4; k++) {
            const int jj = tid * 4 + k;
            const float  bv = b1[jj];
            const float4 wr = reinterpret_cast<const float4*>(W2)[jj];
            o0 += bv * wr.x; o1 += bv * wr.y; o2 += bv * wr.z; o3 += bv * wr.w;
        }
    }

    // fixed-order block reduction (deterministic)
    #pragma unroll
    for (int o = 16; o > 0; o >>= 1) {
        o0 += __shfl_xor_sync(0xffffffffu, o0, o);
        o1 += __shfl_xor_sync(0xffffffffu, o1, o);
        o2 += __shfl_xor_sync(0xffffffffu, o2, o);
        o3 += __shfl_xor_sync(0xffffffffu, o3, o);
    }
    __shared__ float red[4][4];
    const int w = tid >> 5, lane = tid & 31;
    if (lane == 0) { red[w][0] = o0; red[w][1] = o1; red[w][2] = o2; red[w][3] = o3; }
    __syncthreads();
    if (tid < 4) {
        float t = red[0][tid] + red[1][tid] + red[2][tid] + red[3][tid];
        g_outp[b][j][tid] = t;
    }
}

// ============================================================================
// K3: out[b][c] = sum_j g_outp[b][j][c] + b2[c]   (single tiny block)
// ============================================================================
__global__ __launch_bounds__(64) void k3_kernel(
    const float* __restrict__ b2, float* __restrict__ out)
{
    const int tid = threadIdx.x;   // 64 = 16 bags x 4 classes
    const int b = tid >> 2, c = tid & 3;
    float t = b2[c];
    #pragma unroll
    for (int j = 0; j < KSL; j++) t += g_outp[b][j][c];
    out[b * 4 + c] = t;
}

// ---------------- launcher --------------------------------------------------
extern "C" void kernel_launch(void* const* d_in, const int* in_sizes, int n_in,
                              void* d_out, int out_size)
{
    const float* bags  = (const float*)d_in[0];   // [16, 4096, 1024]
    const float* query = (const float*)d_in[1];   // [1024]
    const float* W1    = (const float*)d_in[2];   // [3072, 512]
    const float* b1    = (const float*)d_in[3];   // [512]
    const float* W2    = (const float*)d_in[4];   // [512, 4]
    const float* b2    = (const float*)d_in[5];   // [4]
    float*       out   = (float*)d_out;           // [16, 4]

    k1_kernel<<<Gg + WCB, TPB>>>(bags, query, W1, W2);
    k2_kernel<<<Bb * KSL, 128>>>(b1, W2);
    k3_kernel<<<1, 64>>>(b2, out);
}

// round 5
// speedup vs baseline: 1.1762x; 1.1762x over previous
#include <cuda_runtime.h>
#include <cstdint>

// Problem constants
#define Bb   16
#define Nn   4096
#define Dd   1024
#define Hh   512
#define Cc   4
#define Ss   64                  // chunks per bag
#define ROWS 64                  // rows per chunk (Nn/Ss)
#define TPB  256
#define NCH  (Bb * Ss)           // 1024 chunk CTAs
#define WCB  384                 // Wc CTAs (8 W1-rows each) -- run FIRST
#define TR   4                   // rows per tile
#define NT   (ROWS / TR)         // 16 tiles per chunk
#define STAGES 2                 // cp.async ring depth (2*16KB = 32KB dyn smem)
#define KSL  6                   // k2 slices per bag

// ---------------- scratch (static device arrays; no cudaMalloc) -------------
__device__ float g_Pm[NCH];
__device__ float g_Pl[NCH];
__device__ float g_Pacc[NCH][Dd];
__device__ float g_Psum[NCH][Dd];
__device__ float g_Pmx[NCH][Dd];
__device__ float g_Wc[3 * Dd][Cc];     // W1 @ W2 (head is affine: no activation)
__device__ float g_outp[Bb][KSL][Cc];  // per-slice partial outputs

__device__ __forceinline__ void cp16(uint32_t smem_dst, const float* gsrc) {
    asm volatile("cp.async.cg.shared.global [%0], [%1], 16;\n"
                 :: "r"(smem_dst), "l"(gsrc));
}
__device__ __forceinline__ void cp_commit() {
    asm volatile("cp.async.commit_group;\n");
}
template <int N> __device__ __forceinline__ void cp_wait() {
    asm volatile("cp.async.wait_group %0;\n" :: "n"(N));
}

// ============================================================================
// K1: fused [Wc = W1 @ W2] (blocks 0..WCB) + [pass1 pooling] (blocks WCB..)
//   pass1: one chunk of 64 contiguous rows; cp.async 2-stage ring (16KB/stage);
//   thread t owns d-slots [4t,4t+4). Pipeline depth lives in SMEM, not regs.
// ============================================================================
extern __shared__ float dyn[];   // [STAGES][TR][Dd] = 32768 B (pass1) / sW2 (Wc)

__global__ __launch_bounds__(TPB, 4) void k1_kernel(
    const float* __restrict__ bags, const float* __restrict__ query,
    const float* __restrict__ W1,   const float* __restrict__ W2)
{
    const int blk = blockIdx.x;
    const int tid = threadIdx.x;

    if (blk < WCB) {
        // -------- Wc = W1 @ W2: one warp per W1 row; sW2 aliased onto dyn ---
        float* sW2 = dyn;                       // [Cc][Hh] row-major (8KB)
        for (int i = tid; i < Hh * Cc; i += TPB)
            sW2[(i & 3) * Hh + (i >> 2)] = W2[i];
        __syncthreads();

        const int d    = blk * 8 + (tid >> 5);
        const int lane = tid & 31;
        const float* row = W1 + (long long)d * Hh;

        float a0 = 0.f, a1 = 0.f, a2 = 0.f, a3 = 0.f;
        for (int j = lane; j < Hh; j += 32) {
            const float wv = row[j];
            a0 += wv * sW2[0 * Hh + j]; a1 += wv * sW2[1 * Hh + j];
            a2 += wv * sW2[2 * Hh + j]; a3 += wv * sW2[3 * Hh + j];
        }
        #pragma unroll
        for (int o = 16; o > 0; o >>= 1) {
            a0 += __shfl_xor_sync(0xffffffffu, a0, o);
            a1 += __shfl_xor_sync(0xffffffffu, a1, o);
            a2 += __shfl_xor_sync(0xffffffffu, a2, o);
            a3 += __shfl_xor_sync(0xffffffffu, a3, o);
        }
        if (lane == 0)
            reinterpret_cast<float4*>(g_Wc)[d] = make_float4(a0, a1, a2, a3);
        return;
    }

    // ---------------- pass1 ------------------------------------------------
    const int c = blk - WCB;                    // chunk id (b*Ss + s)
    __shared__ float sd[TR][8];                 // [row][warp] partial dots
    __shared__ __align__(16) float ssc[TR];     // final scores

    const float4 q = reinterpret_cast<const float4*>(query)[tid];

    float4 acc = make_float4(0.f, 0.f, 0.f, 0.f);
    float4 sum = make_float4(0.f, 0.f, 0.f, 0.f);
    float4 mxv = make_float4(-1e30f, -1e30f, -1e30f, -1e30f);
    float  m = -1e30f, l = 0.f;

    const float* base = bags + (long long)c * (ROWS * Dd);   // contiguous chunk
    const uint32_t sbase = (uint32_t)__cvta_generic_to_shared(dyn);
    const int w = tid >> 5, lane = tid & 31;

    // prologue: fill the ring (tiles 0..STAGES-1, one commit group each)
    #pragma unroll
    for (int t = 0; t < STAGES; t++) {
        #pragma unroll
        for (int r = 0; r < TR; r++)
            cp16(sbase + (uint32_t)(((t * TR + r) * Dd + tid * 4) * 4),
                 base + (long long)(t * TR + r) * Dd + tid * 4);
        cp_commit();
    }

    for (int t = 0; t < NT; t++) {
        const int buf = t & 1;
        cp_wait<STAGES - 1>();
        __syncthreads();                        // tile t resident + visible

        // load tile into regs, partial dots
        const float* sb = dyn + buf * (TR * Dd);
        float4 x[TR]; float p[TR];
        #pragma unroll
        for (int r = 0; r < TR; r++) {
            x[r] = *reinterpret_cast<const float4*>(sb + r * Dd + tid * 4);
            p[r] = x[r].x * q.x + x[r].y * q.y + x[r].z * q.z + x[r].w * q.w;
        }
        #pragma unroll
        for (int o = 16; o > 0; o >>= 1)
            #pragma unroll
            for (int r = 0; r < TR; r++)
                p[r] += __shfl_xor_sync(0xffffffffu, p[r], o);
        if (lane == 0)
            #pragma unroll
            for (int r = 0; r < TR; r++) sd[r][w] = p[r];
        __syncthreads();                        // sd ready; dyn[buf] fully read

        // refill this buffer with tile t+STAGES (all reads of buf done)
        const int ft = t + STAGES;
        if (ft < NT) {
            #pragma unroll
            for (int r = 0; r < TR; r++)
                cp16(sbase + (uint32_t)(((buf * TR + r) * Dd + tid * 4) * 4),
                     base + (long long)(ft * TR + r) * Dd + tid * 4);
        }
        cp_commit();                            // commit (possibly empty) group

        if (tid < TR) {                         // stage-2 score reduce
            float tsum = 0.f;
            #pragma unroll
            for (int ww = 0; ww < 8; ww++) tsum += sd[tid][ww];
            ssc[tid] = tsum;
        }
        __syncthreads();

        const float4 s4 = *reinterpret_cast<const float4*>(ssc);
        float sc[TR] = { s4.x, s4.y, s4.z, s4.w };

        // batch-max online softmax: one rescale per tile
        float bm = fmaxf(fmaxf(sc[0], sc[1]), fmaxf(sc[2], sc[3]));
        const float mn   = fmaxf(m, bm);
        const float corr = __expf(m - mn);
        float e[TR];
        #pragma unroll
        for (int r = 0; r < TR; r++) e[r] = __expf(sc[r] - mn);

        l *= corr;
        acc.x *= corr; acc.y *= corr; acc.z *= corr; acc.w *= corr;
        #pragma unroll
        for (int r = 0; r < TR; r++) {
            l += e[r];
            acc.x += e[r] * x[r].x; acc.y += e[r] * x[r].y;
            acc.z += e[r] * x[r].z; acc.w += e[r] * x[r].w;
            sum.x += x[r].x; sum.y += x[r].y;
            sum.z += x[r].z; sum.w += x[r].w;
            mxv.x = fmaxf(mxv.x, x[r].x); mxv.y = fmaxf(mxv.y, x[r].y);
            mxv.z = fmaxf(mxv.z, x[r].z); mxv.w = fmaxf(mxv.w, x[r].w);
        }
        m = mn;
    }

    reinterpret_cast<float4*>(g_Pacc[c])[tid] = acc;
    reinterpret_cast<float4*>(g_Psum[c])[tid] = sum;
    reinterpret_cast<float4*>(g_Pmx[c])[tid]  = mxv;
    if (tid == 0) { g_Pm[c] = m; g_Pl[c] = l; }
}

// ============================================================================
// K2: merge chunk partials + dot with Wc. grid = Bb*KSL (96) x 128 threads.
//   block (b, j): sec = j>>1 (0 mean, 1 max, 2 attn), 128 float4 X-slots.
// ============================================================================
__global__ __launch_bounds__(128) void k2_kernel(
    const float* __restrict__ b1, const float* __restrict__ W2)
{
    const int b   = blockIdx.x / KSL;
    const int j   = blockIdx.x % KSL;
    const int tid = threadIdx.x;
    const int sec = j >> 1;                 // uniform per block
    const int d4  = (j & 1) * 128 + tid;
    const int g0  = b * Ss;

    float4 v;
    if (sec == 0) {
        float4 a = make_float4(0.f, 0.f, 0.f, 0.f);
        #pragma unroll 16
        for (int s = 0; s < Ss; s++) {
            float4 u = reinterpret_cast<const float4*>(g_Psum[g0 + s])[d4];
            a.x += u.x; a.y += u.y; a.z += u.z; a.w += u.w;
        }
        const float invN = 1.f / (float)Nn;
        v = make_float4(a.x * invN, a.y * invN, a.z * invN, a.w * invN);
    } else if (sec == 1) {
        float4 a = make_float4(-1e30f, -1e30f, -1e30f, -1e30f);
        #pragma unroll 16
        for (int s = 0; s < Ss; s++) {
            float4 u = reinterpret_cast<const float4*>(g_Pmx[g0 + s])[d4];
            a.x = fmaxf(a.x, u.x); a.y = fmaxf(a.y, u.y);
            a.z = fmaxf(a.z, u.z); a.w = fmaxf(a.w, u.w);
        }
        v = a;
    } else {
        __shared__ float swe[Ss];
        float M = -1e30f;
        #pragma unroll
        for (int s = 0; s < Ss; s++) M = fmaxf(M, g_Pm[g0 + s]);  // L1-broadcast
        if (tid < Ss) swe[tid] = __expf(g_Pm[g0 + tid] - M);
        __syncthreads();
        float L = 0.f;
        #pragma unroll
        for (int s = 0; s < Ss; s++) L += g_Pl[g0 + s] * swe[s];
        float4 a = make_float4(0.f, 0.f, 0.f, 0.f);
        #pragma unroll 16
        for (int s = 0; s < Ss; s++) {
            const float we = swe[s];
            float4 u = reinterpret_cast<const float4*>(g_Pacc[g0 + s])[d4];
            a.x += u.x * we; a.y += u.y * we; a.z += u.z * we; a.w += u.w * we;
        }
        const float invL = 1.f / L;
        v = make_float4(a.x * invL, a.y * invL, a.z * invL, a.w * invL);
    }

    // dot with 4 Wc rows for this thread's 4 d-slots
    const int    rbase = sec * Dd + d4 * 4;
    const float4 w0 = reinterpret_cast<const float4*>(g_Wc)[rbase + 0];
    const float4 w1 = reinterpret_cast<const float4*>(g_Wc)[rbase + 1];
    const float4 w2 = reinterpret_cast<const float4*>(g_Wc)[rbase + 2];
    const float4 w3 = reinterpret_cast<const float4*>(g_Wc)[rbase + 3];
    float o0 = v.x * w0.x + v.y * w1.x + v.z * w2.x + v.w * w3.x;
    float o1 = v.x * w0.y + v.y * w1.y + v.z * w2.y + v.w * w3.y;
    float o2 = v.x * w0.z + v.y * w1.z + v.z * w2.z + v.w * w3.z;
    float o3 = v.x * w0.w + v.y * w1.w + v.z * w2.w + v.w * w3.w;

    // block (b,0) additionally folds the bias term b1 @ W2
    if (j == 0) {
        #pragma unroll
        for (int k = 0; k < 4; k++) {
            const int jj = tid * 4 + k;
            const float  bv = b1[jj];
            const float4 wr = reinterpret_cast<const float4*>(W2)[jj];
            o0 += bv * wr.x; o1 += bv * wr.y; o2 += bv * wr.z; o3 += bv * wr.w;
        }
    }

    // fixed-order block reduction (deterministic)
    #pragma unroll
    for (int o = 16; o > 0; o >>= 1) {
        o0 += __shfl_xor_sync(0xffffffffu, o0, o);
        o1 += __shfl_xor_sync(0xffffffffu, o1, o);
        o2 += __shfl_xor_sync(0xffffffffu, o2, o);
        o3 += __shfl_xor_sync(0xffffffffu, o3, o);
    }
    __shared__ float red[4][4];
    const int w = tid >> 5, lane = tid & 31;
    if (lane == 0) { red[w][0] = o0; red[w][1] = o1; red[w][2] = o2; red[w][3] = o3; }
    __syncthreads();
    if (tid < 4) {
        g_outp[b][j][tid] = red[0][tid] + red[1][tid] + red[2][tid] + red[3][tid];
    }
}

// ============================================================================
// K3: out[b][c] = sum_j g_outp[b][j][c] + b2[c]
// ============================================================================
__global__ __launch_bounds__(64) void k3_kernel(
    const float* __restrict__ b2, float* __restrict__ out)
{
    const int tid = threadIdx.x;      // 64 = 16 bags x 4 classes
    const int b = tid >> 2, cc = tid & 3;
    float t = b2[cc];
    #pragma unroll
    for (int j = 0; j < KSL; j++) t += g_outp[b][j][cc];
    out[b * 4 + cc] = t;
}

// ---------------- launcher --------------------------------------------------
extern "C" void kernel_launch(void* const* d_in, const int* in_sizes, int n_in,
                              void* d_out, int out_size)
{
    const float* bags  = (const float*)d_in[0];   // [16, 4096, 1024]
    const float* query = (const float*)d_in[1];   // [1024]
    const float* W1    = (const float*)d_in[2];   // [3072, 512]
    const float* b1    = (const float*)d_in[3];   // [512]
    const float* W2    = (const float*)d_in[4];   // [512, 4]
    const float* b2    = (const float*)d_in[5];   // [4]
    float*       out   = (float*)d_out;           // [16, 4]

    const int dynBytes = STAGES * TR * Dd * sizeof(float);   // 32768 B
    k1_kernel<<<WCB + NCH, TPB, dynBytes>>>(bags, query, W1, W2);
    k2_kernel<<<Bb * KSL, 128>>>(b1, W2);
    k3_kernel<<<1, 64>>>(b2, out);
}